// round 16
// baseline (speedup 1.0000x reference)
#include <cuda_runtime.h>
#include <cuda_fp16.h>
#include <cstdint>

#define DIM_K 512
#define NROWS 16384
#define MROWS 4096

// Scratch (no cudaMalloc allowed)
__device__ float g_xsq[NROWS];
__device__ float g_csq[MROWS];
__device__ __half g_Ah[(size_t)NROWS * DIM_K];
__device__ __half g_Bh[(size_t)MROWS * DIM_K];

// ---------------------------------------------------------------------------
// Fused convert(fp32->fp16) + row-norm kernel for BOTH matrices.
// ---------------------------------------------------------------------------
__global__ __launch_bounds__(256)
void conv_kernel(const float* __restrict__ A, const float* __restrict__ B,
                 int N, int M) {
    const int warp = (blockIdx.x * blockDim.x + threadIdx.x) >> 5;
    const int lane = threadIdx.x & 31;
    if (warp >= N + M) return;

    const float* src;
    __half2* dst;
    float* nrm;
    if (warp < N) {
        src = A + (size_t)warp * DIM_K;
        dst = reinterpret_cast<__half2*>(g_Ah + (size_t)warp * DIM_K);
        nrm = &g_xsq[warp];
    } else {
        const int row = warp - N;
        src = B + (size_t)row * DIM_K;
        dst = reinterpret_cast<__half2*>(g_Bh + (size_t)row * DIM_K);
        nrm = &g_csq[row];
    }

    float s = 0.0f;
    #pragma unroll
    for (int i = 0; i < 4; i++) {
        float4 v = reinterpret_cast<const float4*>(src)[lane + i * 32];
        dst[2 * (lane + i * 32) + 0] = __floats2half2_rn(v.x, v.y);
        dst[2 * (lane + i * 32) + 1] = __floats2half2_rn(v.z, v.w);
        s += v.x * v.x + v.y * v.y + v.z * v.z + v.w * v.w;
    }
    #pragma unroll
    for (int off = 16; off > 0; off >>= 1)
        s += __shfl_down_sync(0xffffffffu, s, off);
    if (lane == 0) *nrm = s;
}

// ---------------------------------------------------------------------------
// Legacy tensor-core helpers
// ---------------------------------------------------------------------------
__device__ __forceinline__ uint32_t smem_u32(const void* p) {
    uint32_t a;
    asm("{ .reg .u64 t; cvta.to.shared.u64 t, %1; cvt.u32.u64 %0, t; }"
        : "=r"(a) : "l"(p));
    return a;
}

#define CP16_IMM(sreg, preg, SOFF, GOFF)                                      \
    asm volatile("cp.async.cg.shared.global [%0+" SOFF "], [%1+" GOFF "], 16;" \
                 :: "r"(sreg), "l"(preg) : "memory")

__device__ __forceinline__ void ldsm_x4(uint32_t* r, uint32_t addr) {
    asm volatile("ldmatrix.sync.aligned.m8n8.x4.shared.b16 {%0,%1,%2,%3}, [%4];"
                 : "=r"(r[0]), "=r"(r[1]), "=r"(r[2]), "=r"(r[3]) : "r"(addr));
}

__device__ __forceinline__ void mma16816_h(uint32_t* d, const uint32_t* a,
                                           const uint32_t b0, const uint32_t b1) {
    asm volatile(
        "mma.sync.aligned.m16n8k16.row.col.f16.f16.f16.f16 "
        "{%0,%1}, {%2,%3,%4,%5}, {%6,%7}, {%0,%1};"
        : "+r"(d[0]), "+r"(d[1])
        : "r"(a[0]), "r"(a[1]), "r"(a[2]), "r"(a[3]), "r"(b0), "r"(b1));
}

__device__ __forceinline__ void stcs_f2(float* p, float2 v) {
    asm volatile("st.global.cs.v2.f32 [%0], {%1, %2};"
                 :: "l"(p), "f"(v.x), "f"(v.y) : "memory");
}

__device__ __forceinline__ uint32_t swz(int r, int cb) {
    return (uint32_t)(r * 128 + (cb ^ ((r & 7) << 4)));
}

// ---------------------------------------------------------------------------
// GEMM: CTA 128x256, BK=64, 2-stage ring, 8 warps (64x64), 2 CTAs/SM.
// CUTLASS ordering: wait -> ONE barrier -> issue next loads -> compute.
// Safe because all warps passed the barrier => compute(ks-1) done, and
// load(ks+1) writes stage (ks+1)&1 == (ks-1)&1.
// ---------------------------------------------------------------------------
#define BM 128
#define BN 256
#define BK 64
#define NS (DIM_K / BK)             // 8
#define STAGES 2
#define A_BYTES (BM * 128)          // 16384
#define B_BYTES (BN * 128)          // 32768
#define STAGE_BYTES (A_BYTES + B_BYTES)   // 49152
#define DYN_SMEM (STAGES * STAGE_BYTES + 1024)

__global__ __launch_bounds__(256, 2)
void dist_hmma_kernel(float* __restrict__ C, int M) {
    extern __shared__ char dyn[];
    uint32_t base = (smem_u32(dyn) + 1023u) & ~1023u;

    const int tid  = threadIdx.x;
    const int wid  = tid >> 5;
    const int lane = tid & 31;
    const int rowBase = blockIdx.y * BM;
    const int colBase = blockIdx.x * BN;
    const int wm = (wid & 1) * 64;
    const int wn = (wid >> 1) * 64;

    // ---- loader constants: affine addressing (immediates carry strides) ----
    const int r0  = tid >> 3;
    const int q16 = (tid & 7) * 16;
    const uint32_t sOff = base + (uint32_t)(r0 * 128 + (q16 ^ ((r0 & 7) << 4)));
    const char* pA = (const char*)(g_Ah + (size_t)rowBase * DIM_K)
                     + r0 * 1024 + q16;
    const char* pB = (const char*)(g_Bh + (size_t)colBase * DIM_K)
                     + r0 * 1024 + q16;

    uint32_t acc[4][8][2];
    #pragma unroll
    for (int i = 0; i < 4; i++)
        #pragma unroll
        for (int j = 0; j < 8; j++) {
            acc[i][j][0] = 0u;
            acc[i][j][1] = 0u;
        }

    auto load_stage = [&](int ks) {
        const uint32_t s = sOff + (uint32_t)(ks & 1) * STAGE_BYTES;
        const char* a = pA + ks * (BK * 2);
        const char* b = pB + ks * (BK * 2);
        CP16_IMM(s, a, "0",     "0");
        CP16_IMM(s, a, "4096",  "32768");
        CP16_IMM(s, a, "8192",  "65536");
        CP16_IMM(s, a, "12288", "98304");
        CP16_IMM(s, b, "16384", "0");
        CP16_IMM(s, b, "20480", "32768");
        CP16_IMM(s, b, "24576", "65536");
        CP16_IMM(s, b, "28672", "98304");
        CP16_IMM(s, b, "32768", "131072");
        CP16_IMM(s, b, "36864", "163840");
        CP16_IMM(s, b, "40960", "196608");
        CP16_IMM(s, b, "45056", "229376");
    };

    // prologue: stage 0 in flight
    load_stage(0);
    asm volatile("cp.async.commit_group;" ::: "memory");

    // per-lane fragment addressing, both stages precomputed
    const int fr = (lane & 7) + ((lane >> 3) & 1) * 8;
    const int fc = (lane >> 4) * 16;

    uint32_t aAd[STAGES][4], bAd[STAGES][4];
    #pragma unroll
    for (int st = 0; st < STAGES; st++) {
        const uint32_t sb = base + st * STAGE_BYTES;
        #pragma unroll
        for (int mi = 0; mi < 4; mi++)
            aAd[st][mi] = sb + swz(wm + mi * 16 + fr, fc);
        #pragma unroll
        for (int j = 0; j < 4; j++)
            bAd[st][j] = sb + A_BYTES + swz(wn + j * 16 + fr, fc);
    }

    for (int ks = 0; ks < NS; ks++) {
        // stage ks data arrived (it is the only outstanding group)
        asm volatile("cp.async.wait_group 0;" ::: "memory");
        __syncthreads();   // also: all warps finished compute(ks-1)

        // issue next slab's loads into the stage everyone just vacated
        if (ks + 1 < NS) load_stage(ks + 1);
        asm volatile("cp.async.commit_group;" ::: "memory");

        const int st = ks & (STAGES - 1);

        #pragma unroll
        for (int kk = 0; kk < 4; kk++) {
            const uint32_t x = (uint32_t)(kk << 5);   // SW128: flips bits 5-6
            uint32_t aF[4][4], bR[4][4];
            #pragma unroll
            for (int mi = 0; mi < 4; mi++)
                ldsm_x4(aF[mi], aAd[st][mi] ^ x);
            #pragma unroll
            for (int j = 0; j < 4; j++)
                ldsm_x4(bR[j], bAd[st][j] ^ x);
            #pragma unroll
            for (int mi = 0; mi < 4; mi++) {
                #pragma unroll
                for (int j = 0; j < 4; j++) {
                    mma16816_h(acc[mi][2 * j + 0], aF[mi], bR[j][0], bR[j][2]);
                    mma16816_h(acc[mi][2 * j + 1], aF[mi], bR[j][1], bR[j][3]);
                }
            }
        }
    }

    // ---- epilogue: out = xsq + csq - 2*dot, streaming float2 stores ----
    #pragma unroll
    for (int mi = 0; mi < 4; mi++) {
        const int row0 = rowBase + wm + mi * 16 + (lane >> 2);
        const float xs0 = g_xsq[row0];
        const float xs1 = g_xsq[row0 + 8];
        #pragma unroll
        for (int nj = 0; nj < 8; nj++) {
            const int col0 = colBase + wn + nj * 8 + (lane & 3) * 2;
            const float2 cs = *reinterpret_cast<const float2*>(&g_csq[col0]);
            float2 d0 = __half22float2(*reinterpret_cast<__half2*>(&acc[mi][nj][0]));
            float2 d1 = __half22float2(*reinterpret_cast<__half2*>(&acc[mi][nj][1]));
            float2 o0, o1;
            o0.x = xs0 + cs.x - 2.0f * d0.x;
            o0.y = xs0 + cs.y - 2.0f * d0.y;
            o1.x = xs1 + cs.x - 2.0f * d1.x;
            o1.y = xs1 + cs.y - 2.0f * d1.y;
            stcs_f2(C + (size_t)row0 * M + col0, o0);
            stcs_f2(C + (size_t)(row0 + 8) * M + col0, o1);
        }
    }
}

// ---------------------------------------------------------------------------
extern "C" void kernel_launch(void* const* d_in, const int* in_sizes, int n_in,
                              void* d_out, int out_size) {
    const float* A = (const float*)d_in[0];
    const float* B = (const float*)d_in[1];
    float* C = (float*)d_out;

    int N = in_sizes[0] / DIM_K;              // 16384
    int M = in_sizes[1] / DIM_K;              // 4096

    cudaFuncSetAttribute(dist_hmma_kernel,
                         cudaFuncAttributeMaxDynamicSharedMemorySize, DYN_SMEM);

    int totalWarps = N + M;                   // 20480
    int blocks = (totalWarps * 32 + 255) / 256;
    conv_kernel<<<blocks, 256>>>(A, B, N, M);

    dim3 grid(M / BN, N / BM);                // (16, 128)
    dist_hmma_kernel<<<grid, 256, DYN_SMEM>>>(C, M);
}